// round 13
// baseline (speedup 1.0000x reference)
#include <cuda_runtime.h>
#include <cuda_fp16.h>
#include <cstdint>

// Input [32, 512, 512, 3] float32 NHWC, 3x3 median, replicate border.
constexpr int Bn  = 32;
constexpr int H   = 512;
constexpr int W   = 512;
constexpr int C   = 3;
constexpr int ROW = W * C;             // 1536 floats per image row
constexpr int IMG = H * ROW;
constexpr int EPT = 8;                 // wc outputs per thread per row
constexpr int TPR = ROW / EPT;         // 192 slots per row
constexpr int PPT = 8;                 // row-pairs per thread (16 output rows)
constexpr int GROUPS = (H / 2) / PPT;  // 32 pair-groups per image
constexpr int BLOCK = 32;              // one warp per block
constexpr int WPR   = TPR / 32;        // 6 warps per row-group
constexpr int NBLK  = Bn * GROUPS * WPR;  // 6144 blocks

constexpr int SEG   = 272;             // floats staged per row (warp window + halo)
constexpr int NQ    = SEG / 4;         // 68 float4 per row
constexpr int QMAX  = NQ - 1 + ((NQ - 1) >> 3);  // 75 after swizzle
constexpr int ROWB  = (QMAX + 1) * 16; // 1216 bytes per staged row
constexpr int RING  = 8;               // ring of 8 rows (2 groups in flight + consume)

__device__ __forceinline__ __half2 med3h2(__half2 a, __half2 b, __half2 c) {
    __half2 mn = __hmin2(a, b);
    __half2 mx = __hmax2(a, b);
    return __hmax2(mn, __hmin2(mx, c));
}
__device__ __forceinline__ __half2 prmt_h2(__half2 a, __half2 b) {
    unsigned int au = *reinterpret_cast<unsigned int*>(&a);
    unsigned int bu = *reinterpret_cast<unsigned int*>(&b);
    unsigned int r  = __byte_perm(au, bu, 0x5432);
    return *reinterpret_cast<__half2*>(&r);
}
__device__ __forceinline__ void cp16(unsigned saddr, const void* g) {
    asm volatile("cp.async.cg.shared.global [%0], [%1], 16;" :: "r"(saddr), "l"(g));
}
#define CP_COMMIT() asm volatile("cp.async.commit_group;")
#define CP_WAIT(N)  asm volatile("cp.async.wait_group %0;" :: "n"(N))

// Edge-replicate remap (mode 0 = passthrough; mode uniform per thread).
__device__ __forceinline__ void remap(const float t[16], int mode, float w[16]) {
    if (mode == 0) {
        #pragma unroll
        for (int k = 0; k < 16; k++) w[k] = t[k];
    } else if (mode == 1) {
        w[0] = t[0]; w[1] = t[0]; w[2] = t[1]; w[3] = t[2];
        #pragma unroll
        for (int k = 4; k < 16; k++) w[k] = t[k - 4];
    } else {
        #pragma unroll
        for (int k = 0; k < 12; k++) w[k] = t[k + 4];
        w[12] = t[13]; w[13] = t[14]; w[14] = t[15]; w[15] = t[15];
    }
}

// Column sorts + pair-shared horizontal combine + streaming store of one row pair.
__device__ __forceinline__ void process_store(const __half2* x, const __half2* y,
                                              const __half2* z, float* o) {
    __half2 mn[15], md[15], mx[15];
    #pragma unroll
    for (int k = 1; k <= 14; k++) {
        __half2 lo2 = __hmin2(y[k], z[k]);
        __half2 hi2 = __hmax2(y[k], z[k]);
        mn[k] = __hmin2(x[k], lo2);
        mx[k] = __hmax2(x[k], hi2);
        md[k] = __hmax2(lo2, __hmin2(x[k], hi2));
    }
    __half2 qlo[9], qhi[9], qa[9], qb[9];
    #pragma unroll
    for (int k = 4; k <= 8; k++) {
        qlo[k] = __hmax2(mn[k], mn[k + 3]);
        qhi[k] = __hmin2(mx[k], mx[k + 3]);
        qa[k]  = __hmin2(md[k], md[k + 3]);
        qb[k]  = __hmax2(md[k], md[k + 3]);
    }
    float r0[EPT], r1[EPT];
    #pragma unroll
    for (int j = 0; j < EPT; j++) {
        int kp = (j < 4) ? (j + 4) : (j + 1);
        int ks = (j < 4) ? (j + 1) : (j + 7);
        __half2 lo = __hmax2(qlo[kp], mn[ks]);
        __half2 hi = __hmin2(qhi[kp], mx[ks]);
        __half2 mi = __hmax2(qa[kp], __hmin2(md[ks], qb[kp]));
        __half2 m  = med3h2(lo, mi, hi);
        float2 f = __half22float2(m);
        r0[j] = f.x;
        r1[j] = f.y;
    }
    float4* po0 = reinterpret_cast<float4*>(o);
    float4* po1 = reinterpret_cast<float4*>(o + ROW);
    __stcs(po0 + 0, make_float4(r0[0], r0[1], r0[2], r0[3]));
    __stcs(po0 + 1, make_float4(r0[4], r0[5], r0[6], r0[7]));
    __stcs(po1 + 0, make_float4(r1[0], r1[1], r1[2], r1[3]));
    __stcs(po1 + 1, make_float4(r1[4], r1[5], r1[6], r1[7]));
}

__global__ void __launch_bounds__(BLOCK, 16)
median3x3_smem_kernel(const float* __restrict__ in, float* __restrict__ out) {
    __shared__ __align__(16) char smem[RING * ROWB];

    int lane = threadIdx.x;
    int wid  = blockIdx.x;
    int w    = wid % WPR;
    int rest = wid / WPR;
    int g    = rest % GROUPS;
    int b    = rest / GROUPS;
    int h0   = g * (2 * PPT);
    int slot0 = w * 32;
    int wc0  = (slot0 + lane) * EPT;

    int mode = (wc0 == 0) ? 1 : ((wc0 == ROW - EPT) ? 2 : 0);
    int base = (mode == 0) ? (wc0 - 4) : ((mode == 1) ? 0 : (ROW - 16));
    // staged segment origin in row-float coords (w=0 uses virtual -4; never read q=0)
    int seg_base = (w == 0) ? -4 : ((w == WPR - 1) ? (ROW - SEG) : (slot0 * 8 - 4));

    // per-thread read offsets (4 float4s of the 16-float window), swizzled
    int q_rd = (base - seg_base) >> 2;
    int roff0 = ((q_rd + 0) + ((q_rd + 0) >> 3)) * 16;
    int roff1 = ((q_rd + 1) + ((q_rd + 1) >> 3)) * 16;
    int roff2 = ((q_rd + 2) + ((q_rd + 2) >> 3)) * 16;
    int roff3 = ((q_rd + 3) + ((q_rd + 3) >> 3)) * 16;

    // per-thread write slots for staging (68 float4 over 32 lanes), swizzled
    int q0 = lane, q1 = lane + 32, q2 = lane + 64;
    int woff0 = (q0 + (q0 >> 3)) * 16;
    int woff1 = (q1 + (q1 >> 3)) * 16;
    int woff2 = (q2 + (q2 >> 3)) * 16;
    bool p0 = (seg_base + 4 * q0) >= 0;   // false only for w==0, lane==0
    bool p2 = (q2 < NQ);                  // lanes 0..3

    unsigned sbase = (unsigned)__cvta_generic_to_shared(smem);
    const float* img = in + (int64_t)b * IMG;
    float* o = out + (int64_t)b * IMG + (int64_t)h0 * ROW + wc0;

    // stage one row (load index li -> ring slot li&7), coalesced cp.async
    auto stage_row = [&](int li) {
        int hr = min(max(h0 - 1 + li, 0), H - 1);
        const float* rp = img + (int64_t)hr * ROW + seg_base;
        unsigned srow = sbase + (unsigned)((li & (RING - 1)) * ROWB);
        if (p0) cp16(srow + woff0, rp + 4 * q0);
        cp16(srow + woff1, rp + 4 * q1);
        if (p2) cp16(srow + woff2, rp + 4 * q2);
    };
    // read this thread's 16-float window from a staged row
    auto load_seg = [&](int slot, float t[16]) {
        const char* rb = smem + slot * ROWB;
        float4 a4 = *reinterpret_cast<const float4*>(rb + roff0);
        float4 b4 = *reinterpret_cast<const float4*>(rb + roff1);
        float4 c4 = *reinterpret_cast<const float4*>(rb + roff2);
        float4 d4 = *reinterpret_cast<const float4*>(rb + roff3);
        t[0]=a4.x; t[1]=a4.y; t[2]=a4.z; t[3]=a4.w;
        t[4]=b4.x; t[5]=b4.y; t[6]=b4.z; t[7]=b4.w;
        t[8]=c4.x; t[9]=c4.y; t[10]=c4.z; t[11]=c4.w;
        t[12]=d4.x; t[13]=d4.y; t[14]=d4.z; t[15]=d4.w;
    };

    // ---- issue staging: G0 = rows(li 0..3), G1 = (4,5), G2 = (6,7) ----
    stage_row(0); stage_row(1); stage_row(2); stage_row(3); CP_COMMIT();
    stage_row(4); stage_row(5); CP_COMMIT();
    stage_row(6); stage_row(7); CP_COMMIT();

    __half2 x[15], y[15], zA[15], zB[15];

    // ---- prologue: pair 0 from ring slots 0..3 ----
    CP_WAIT(2); __syncwarp();
    {
        float t[16], wa[16], wb[16];
        load_seg(0, t); remap(t, mode, wa);
        load_seg(1, t); remap(t, mode, wb);
        #pragma unroll
        for (int k = 1; k <= 14; k++) x[k] = __floats2half2_rn(wa[k], wb[k]);   // (h-1|h)
        load_seg(2, t); remap(t, mode, wa);
        #pragma unroll
        for (int k = 1; k <= 14; k++) y[k] = __floats2half2_rn(wb[k], wa[k]);   // (h|h+1)
        load_seg(3, t); remap(t, mode, wb);
        #pragma unroll
        for (int k = 1; k <= 14; k++) zA[k] = __floats2half2_rn(wa[k], wb[k]);  // (h+1|h+2)
        process_store(x, y, zA, o);
        o += 2 * ROW;
    }

    // ---- march step i: consume group G_i (rows li 2i+2, 2i+3) ----
    auto body = [&](const __half2* zin, __half2* zout, int i) {
        float t[16], w1[16], w2[16];
        load_seg((2 * i + 2) & (RING - 1), t); remap(t, mode, w1);
        load_seg((2 * i + 3) & (RING - 1), t); remap(t, mode, w2);
        __half2 yn[15];
        #pragma unroll
        for (int k = 1; k <= 14; k++) {
            zout[k] = __floats2half2_rn(w1[k], w2[k]);   // (h+1 | h+2)
            yn[k]   = prmt_h2(zin[k], zout[k]);          // (h   | h+1)
        }
        process_store(zin, yn, zout, o);
        o += 2 * ROW;
    };

    // steps 1..5: stage two-ahead group, wait so that current group is complete
    stage_row(8);  stage_row(9);  CP_COMMIT(); CP_WAIT(2); __syncwarp(); body(zA, zB, 1);
    stage_row(10); stage_row(11); CP_COMMIT(); CP_WAIT(2); __syncwarp(); body(zB, zA, 2);
    stage_row(12); stage_row(13); CP_COMMIT(); CP_WAIT(2); __syncwarp(); body(zA, zB, 3);
    stage_row(14); stage_row(15); CP_COMMIT(); CP_WAIT(2); __syncwarp(); body(zB, zA, 4);
    stage_row(16); stage_row(17); CP_COMMIT(); CP_WAIT(2); __syncwarp(); body(zA, zB, 5);
    // steps 6,7: nothing left to stage; drain
    CP_WAIT(1); __syncwarp(); body(zB, zA, 6);
    CP_WAIT(0); __syncwarp(); body(zA, zB, 7);
}

extern "C" void kernel_launch(void* const* d_in, const int* in_sizes, int n_in,
                              void* d_out, int out_size) {
    const float* in = (const float*)d_in[0];
    float* out = (float*)d_out;
    median3x3_smem_kernel<<<NBLK, BLOCK>>>(in, out);   // 6144 blocks x 32
}